// round 12
// baseline (speedup 1.0000x reference)
#include <cuda_runtime.h>
#include <cstdint>

#define BB 2
#define LSEQ 2048
#define DM 512
#define DI 1024
#define DSTATE 16
#define DTR 32
#define FF 1024
#define NL 2
#define M_TOT (BB*LSEQ)   // 4096
#define KSPLIT 16

// ---------------- scratch (static device globals; no allocation) ----------------
__device__ float g_xz [BB*LSEQ*2*DI];   // in_proj output: [B,L,2*DI] (xin | z)
__device__ float g_xc [BB*LSEQ*DI];     // conv+silu, [B,L,DI]
__device__ float g_xcT[BB*LSEQ*DI];     // conv+silu, transposed [B,DI,L]
__device__ float g_dbl[BB*LSEQ*64];     // x_proj dt cols [B*L][64-stride] (0..31 used)
__device__ float g_bc [BB*LSEQ*32];     // interleaved (B,C) pairs [B*L][16] float2
__device__ float g_dtT[BB*LSEQ*DI];     // softplus(dt) transposed [B,DI,L]
__device__ float g_yg [BB*LSEQ*DI];     // gated y [B,L,DI] (tf32-rounded)
__device__ float g_x1 [BB*LSEQ*DM];
__device__ float g_x2 [BB*LSEQ*DM];
__device__ float g_ff [BB*LSEQ*FF];     // MLP hidden; ALSO xproj split-K scratch (16MB)
// tf32-rounded copies of GEMM operands
__device__ float g_rx  [M_TOT*DM];
__device__ float g_ripw[NL*2*DI*DM];
__device__ float g_ropw[NL*DM*DI];
__device__ float g_rw1 [FF*DM];
__device__ float g_rw2 [DM*FF];

__device__ __forceinline__ float siluf(float x) { return x / (1.f + __expf(-x)); }

__device__ __forceinline__ uint32_t f2tf32(float x) {
    uint32_t r;
    asm("cvt.rna.tf32.f32 %0, %1;" : "=r"(r) : "f"(x));
    return r;
}
__device__ __forceinline__ float roundtf(float x) { return __uint_as_float(f2tf32(x)); }

__device__ __forceinline__ void mma_tf32(float* d, const uint32_t* a, const uint32_t* b) {
    asm volatile(
        "mma.sync.aligned.m16n8k8.row.col.f32.tf32.tf32.f32 "
        "{%0,%1,%2,%3}, {%4,%5,%6,%7}, {%8,%9}, {%0,%1,%2,%3};"
        : "+f"(d[0]), "+f"(d[1]), "+f"(d[2]), "+f"(d[3])
        : "r"(a[0]), "r"(a[1]), "r"(a[2]), "r"(a[3]), "r"(b[0]), "r"(b[1]));
}

__device__ __forceinline__ void cp16(void* smem_dst, const void* gptr) {
    uint32_t s = (uint32_t)__cvta_generic_to_shared(smem_dst);
    asm volatile("cp.async.cg.shared.global [%0], [%1], 16;" :: "r"(s), "l"(gptr));
}

__device__ __forceinline__ void ldsm_x4(uint32_t& r0, uint32_t& r1, uint32_t& r2, uint32_t& r3,
                                        uint32_t addr) {
    asm volatile("ldmatrix.sync.aligned.m8n8.x4.shared.b16 {%0,%1,%2,%3}, [%4];"
        : "=r"(r0), "=r"(r1), "=r"(r2), "=r"(r3) : "r"(addr));
}
__device__ __forceinline__ void ldsm_x2(uint32_t& r0, uint32_t& r1, uint32_t addr) {
    asm volatile("ldmatrix.sync.aligned.m8n8.x2.shared.b16 {%0,%1}, [%2];"
        : "=r"(r0), "=r"(r1) : "r"(addr));
}

// ---------------- fused tf32 rounding over 5 segments -----------------------------
__global__ void round_all_kernel(const float* a0, float* b0, int n0,
                                 const float* a1, float* b1, int n1,
                                 const float* a2, float* b2, int n2,
                                 const float* a3, float* b3, int n3,
                                 const float* a4, float* b4, int n4)
{
    int i = blockIdx.x*blockDim.x + threadIdx.x;
    const float* src; float* dst;
    if (i < n0)              { src = a0; dst = b0; }
    else if ((i -= n0) < n1) { src = a1; dst = b1; }
    else if ((i -= n1) < n2) { src = a2; dst = b2; }
    else if ((i -= n2) < n3) { src = a3; dst = b3; }
    else if ((i -= n3) < n4) { src = a4; dst = b4; }
    else return;
    float4 v = reinterpret_cast<const float4*>(src)[i];
    v.x = roundtf(v.x); v.y = roundtf(v.y); v.z = roundtf(v.z); v.w = roundtf(v.w);
    reinterpret_cast<float4*>(dst)[i] = v;
}

// ---------------- TF32 GEMM: 2-stage cp.async + ldmatrix (measured-good) ----------
// C = A * W^T (+bias)(+Cadd)(relu)(roundOut).  A,W pre-rounded to tf32 values.
// A:[M,K] rm, W:[N,K] rm, C:[M,N]. Block 128x128x32, 8 warps, warp tile 64x32.
// Requires: M%128==0, N%128==0, K%32==0. Dynamic smem: 73728 bytes.
__global__ __launch_bounds__(256, 2)
void tf32_gemm_async(const float* __restrict__ A, const float* __restrict__ W,
                     const float* __restrict__ bias, const float* __restrict__ Cadd,
                     float* __restrict__ C, int M, int N, int K, int relu, int roundOut)
{
    extern __shared__ __align__(16) float smem[];
    float* As = smem;                 // [2][128*36]
    float* Bs = smem + 2*128*36;      // [2][128*36]

    const int tid  = threadIdx.x;
    const int warp = tid >> 5, lane = tid & 31;
    const int g = lane >> 2, t = lane & 3;
    const int wm = (warp >> 2) * 64;   // 0 or 64
    const int wn = (warp & 3) * 32;    // 0..96
    const int bm = blockIdx.y * 128;
    const int bn = blockIdx.x * 128;

    // per-lane ldmatrix address offsets (bytes)
    const int rowA = (lane & 7) + (((lane >> 3) & 1) << 3);
    const int colA = ((lane >> 4) & 1) << 2;
    const uint32_t offA = (uint32_t)(rowA*36 + colA) * 4u;
    const int lb = lane & 15;
    const uint32_t offB = (uint32_t)((lb & 7)*36 + ((lb >> 3) << 2)) * 4u;

    const uint32_t As_u = (uint32_t)__cvta_generic_to_shared(As);
    const uint32_t Bs_u = (uint32_t)__cvta_generic_to_shared(Bs);
    const uint32_t STAGE = 128*36*4;

    float d[4][4][4];
#pragma unroll
    for (int mi = 0; mi < 4; mi++)
#pragma unroll
        for (int ni = 0; ni < 4; ni++)
#pragma unroll
            for (int r = 0; r < 4; r++) d[mi][ni][r] = 0.f;

    auto issue_tile = [&](int stage, int k0) {
#pragma unroll
        for (int i = 0; i < 4; i++) {
            int linear = tid + i*256;          // 0..1023 float4 slots
            int m  = linear >> 3;
            int kc = (linear & 7) * 4;
            cp16(&As[stage*128*36 + m*36 + kc], &A[(bm + m)*K + k0 + kc]);
            cp16(&Bs[stage*128*36 + m*36 + kc], &W[(bn + m)*K + k0 + kc]);
        }
    };

    issue_tile(0, 0);
    asm volatile("cp.async.commit_group;");

    const int KT = K >> 5;
    for (int kt = 0; kt < KT; kt++) {
        const int cur = kt & 1;
        if (kt + 1 < KT) {
            issue_tile(cur ^ 1, (kt + 1) << 5);
            asm volatile("cp.async.commit_group;");
            asm volatile("cp.async.wait_group 1;");
        } else {
            asm volatile("cp.async.wait_group 0;");
        }
        __syncthreads();

        const uint32_t Acur = As_u + cur*STAGE;
        const uint32_t Bcur = Bs_u + cur*STAGE;
#pragma unroll
        for (int ks = 0; ks < 4; ks++) {
            const int kk = ks * 8;
            uint32_t a[4][4], b[4][2];
#pragma unroll
            for (int mi = 0; mi < 4; mi++)
                ldsm_x4(a[mi][0], a[mi][1], a[mi][2], a[mi][3],
                        Acur + (uint32_t)(((wm + mi*16)*36 + kk) << 2) + offA);
#pragma unroll
            for (int ni = 0; ni < 4; ni++)
                ldsm_x2(b[ni][0], b[ni][1],
                        Bcur + (uint32_t)(((wn + ni*8)*36 + kk) << 2) + offB);
#pragma unroll
            for (int mi = 0; mi < 4; mi++)
#pragma unroll
                for (int ni = 0; ni < 4; ni++)
                    mma_tf32(d[mi][ni], a[mi], b[ni]);
        }
        __syncthreads();
    }

    // epilogue: c0=(g,2t) c1=(g,2t+1) c2=(g+8,2t) c3=(g+8,2t+1)
#pragma unroll
    for (int mi = 0; mi < 4; mi++) {
        int row0 = bm + wm + mi*16 + g;
        int row1 = row0 + 8;
#pragma unroll
        for (int ni = 0; ni < 4; ni++) {
            int col = bn + wn + ni*8 + 2*t;
            float c0 = d[mi][ni][0], c1 = d[mi][ni][1];
            float c2 = d[mi][ni][2], c3 = d[mi][ni][3];
            if (bias) {
                float b0 = bias[col], b1 = bias[col+1];
                c0 += b0; c1 += b1; c2 += b0; c3 += b1;
            }
            if (Cadd) {
                float2 r0 = *reinterpret_cast<const float2*>(&Cadd[row0*N + col]);
                float2 r1 = *reinterpret_cast<const float2*>(&Cadd[row1*N + col]);
                c0 += r0.x; c1 += r0.y; c2 += r1.x; c3 += r1.y;
            }
            if (relu) {
                c0 = fmaxf(c0, 0.f); c1 = fmaxf(c1, 0.f);
                c2 = fmaxf(c2, 0.f); c3 = fmaxf(c3, 0.f);
            }
            if (roundOut) {
                c0 = roundtf(c0); c1 = roundtf(c1);
                c2 = roundtf(c2); c3 = roundtf(c3);
            }
            *reinterpret_cast<float2*>(&C[row0*N + col]) = make_float2(c0, c1);
            *reinterpret_cast<float2*>(&C[row1*N + col]) = make_float2(c2, c3);
        }
    }
}

// ---------------- x_proj split-K partials: proven sgemm body, K chunk per block ---
// grid (KSPLIT, M_TOT/64). part[(ks*M_TOT + row)*64 + col] = A[rows, kchunk] @ W^T.
__global__ __launch_bounds__(256)
void xproj_part_kernel(const float* __restrict__ A, const float* __restrict__ W,
                       float* __restrict__ part)
{
    constexpr int BM = 64, BN = 64, BK = 8, TM = 4, TN = 4;
    constexpr int THREADS = (BM/TM)*(BN/TN);
    __shared__ __align__(16) float As[BK][BM];
    __shared__ __align__(16) float Bs[BK][BN];
    const int tid = threadIdx.x;
    const int ks = blockIdx.x;
    const int bm = blockIdx.y * BM;
    const int kbeg = ks * (DI / KSPLIT);
    const int kend = kbeg + (DI / KSPLIT);
    const int tni = tid % (BN/TN);
    const int tmi = tid / (BN/TN);

    float acc[TM][TN];
#pragma unroll
    for (int i = 0; i < TM; i++)
#pragma unroll
        for (int j = 0; j < TN; j++) acc[i][j] = 0.f;

    for (int k0 = kbeg; k0 < kend; k0 += BK) {
#pragma unroll
        for (int i = 0; i < (BM*BK)/THREADS; i++) {
            int idx = tid + i*THREADS;
            int m = idx / BK, k = idx % BK;
            As[k][m] = A[(bm + m)*DI + k0 + k];
        }
#pragma unroll
        for (int i = 0; i < (BN*BK)/THREADS; i++) {
            int idx = tid + i*THREADS;
            int n = idx / BK, k = idx % BK;
            Bs[k][n] = W[n*DI + k0 + k];
        }
        __syncthreads();
#pragma unroll
        for (int k = 0; k < BK; k++) {
            float rm[TM], rn[TN];
#pragma unroll
            for (int i = 0; i < TM/4; i++) {
                float4 v = *reinterpret_cast<const float4*>(&As[k][tmi*TM + 4*i]);
                rm[4*i] = v.x; rm[4*i+1] = v.y; rm[4*i+2] = v.z; rm[4*i+3] = v.w;
            }
#pragma unroll
            for (int i = 0; i < TN/4; i++) {
                float4 v = *reinterpret_cast<const float4*>(&Bs[k][tni*TN + 4*i]);
                rn[4*i] = v.x; rn[4*i+1] = v.y; rn[4*i+2] = v.z; rn[4*i+3] = v.w;
            }
#pragma unroll
            for (int i = 0; i < TM; i++)
#pragma unroll
                for (int j = 0; j < TN; j++)
                    acc[i][j] = fmaf(rm[i], rn[j], acc[i][j]);
        }
        __syncthreads();
    }
#pragma unroll
    for (int i = 0; i < TM; i++) {
        int row = bm + tmi*TM + i;
#pragma unroll
        for (int j = 0; j < TN/4; j++) {
            float4 v = make_float4(acc[i][4*j], acc[i][4*j+1], acc[i][4*j+2], acc[i][4*j+3]);
            *reinterpret_cast<float4*>(&part[((size_t)ks*M_TOT + row)*64 + tni*TN + 4*j]) = v;
        }
    }
}

// ---------------- x_proj reduce: sum KSPLIT partials, route dt / interleaved bc ---
__global__ void xproj_reduce_kernel(const float* __restrict__ part,
                                    float* __restrict__ dbl, float* __restrict__ bc)
{
    int i = blockIdx.x*blockDim.x + threadIdx.x;   // M_TOT*16 threads
    int row = i >> 4, cg = i & 15;                 // cg = col/4
    const float4* p = reinterpret_cast<const float4*>(part);
    float4 s = p[((size_t)0*M_TOT + row)*16 + cg];
#pragma unroll
    for (int ks = 1; ks < KSPLIT; ks++) {
        float4 v = p[((size_t)ks*M_TOT + row)*16 + cg];
        s.x += v.x; s.y += v.y; s.z += v.z; s.w += v.w;
    }
    int col = cg * 4;
    if (col < 32) {
        *reinterpret_cast<float4*>(&dbl[row*64 + col]) = s;
    } else if (col < 48) {
        int sidx = col - 32;
        bc[(row*16 + sidx + 0)*2] = s.x;
        bc[(row*16 + sidx + 1)*2] = s.y;
        bc[(row*16 + sidx + 2)*2] = s.z;
        bc[(row*16 + sidx + 3)*2] = s.w;
    } else {
        int sidx = col - 48;
        bc[(row*16 + sidx + 0)*2 + 1] = s.x;
        bc[(row*16 + sidx + 1)*2 + 1] = s.y;
        bc[(row*16 + sidx + 2)*2 + 1] = s.z;
        bc[(row*16 + sidx + 3)*2 + 1] = s.w;
    }
}

// ---------------- causal depthwise conv(4) + silu; writes [B,L,DI] and [B,DI,L] ---
__global__ void conv_silu_kernel(const float* __restrict__ cw, const float* __restrict__ cb)
{
    __shared__ float sx[35][32];
    __shared__ float so[32][33];
    const int b = blockIdx.z, l0 = blockIdx.y*32, d0 = blockIdx.x*32;
    const int tx = threadIdx.x, ty = threadIdx.y;
    const int tid = ty*32 + tx;

    for (int i = tid; i < 35*32; i += 256) {
        int r = i >> 5, dd = i & 31;
        int l = l0 - 3 + r;
        sx[r][dd] = (l >= 0) ? g_xz[(b*LSEQ + l)*2*DI + d0 + dd] : 0.f;
    }
    const float w0 = cw[(d0+tx)*4+0], w1 = cw[(d0+tx)*4+1];
    const float w2 = cw[(d0+tx)*4+2], w3 = cw[(d0+tx)*4+3];
    const float bias = cb[d0+tx];
    __syncthreads();
#pragma unroll
    for (int j = 0; j < 4; j++) {
        int ll = ty + j*8;
        float a = bias + sx[ll][tx]*w0 + sx[ll+1][tx]*w1 + sx[ll+2][tx]*w2 + sx[ll+3][tx]*w3;
        float v = siluf(a);
        g_xc[(b*LSEQ + l0 + ll)*DI + d0 + tx] = v;
        so[ll][tx] = v;
    }
    __syncthreads();
#pragma unroll
    for (int j = 0; j < 4; j++) {
        int dd = ty + j*8;
        g_xcT[(b*DI + d0 + dd)*LSEQ + l0 + tx] = so[tx][dd];
    }
}

// ---------------- dt = softplus(dbl[:, :32] @ dpw^T + dpb), transposed store ------
// r-outer / j-inner interchange: per r, 1 conflict-free LDS (sw) + 4 broadcast LDS
// (sdbl) + 4 FMA. FMA order over r preserved per output -> bit-identical.
__global__ void dtproj_kernel(const float* __restrict__ dpw, const float* __restrict__ dpb)
{
    __shared__ float sdbl[32][33];
    __shared__ float sw  [32][33];
    __shared__ float so  [32][33];
    const int b = blockIdx.z, l0 = blockIdx.y*32, d0 = blockIdx.x*32;
    const int tx = threadIdx.x, ty = threadIdx.y;
    const int tid = ty*32 + tx;

    for (int i = tid; i < 1024; i += 256) {
        int r = i >> 5, c = i & 31;
        sdbl[r][c] = g_dbl[(b*LSEQ + l0 + r)*64 + c];
        sw[r][c]   = dpw[(d0 + r)*32 + c];
    }
    __syncthreads();
    const float bias = dpb[d0 + tx];
    float a0 = bias, a1 = bias, a2 = bias, a3 = bias;
#pragma unroll
    for (int r = 0; r < 32; r++) {
        float wv = sw[tx][r];
        a0 = fmaf(sdbl[ty     ][r], wv, a0);
        a1 = fmaf(sdbl[ty +  8][r], wv, a1);
        a2 = fmaf(sdbl[ty + 16][r], wv, a2);
        a3 = fmaf(sdbl[ty + 24][r], wv, a3);
    }
    so[ty     ][tx] = (a0 > 20.f) ? a0 : log1pf(__expf(a0));
    so[ty +  8][tx] = (a1 > 20.f) ? a1 : log1pf(__expf(a1));
    so[ty + 16][tx] = (a2 > 20.f) ? a2 : log1pf(__expf(a2));
    so[ty + 24][tx] = (a3 > 20.f) ? a3 : log1pf(__expf(a3));
    __syncthreads();
#pragma unroll
    for (int j = 0; j < 4; j++) {
        int dd = ty + j*8;
        g_dtT[(b*DI + d0 + dd)*LSEQ + l0 + tx] = so[tx][dd];
    }
}

// ---------------- selective scan + fused gating -----------------------------------
// thread per (b, d, s); 16-lane reduce; s==0 lane applies silu(z) gate and writes
// g_yg[b,l,d] directly (z prefetched one l4-iteration ahead, off the h-chain).
__global__ void scan_gate_kernel(const float* __restrict__ Alog, const float* __restrict__ Dp)
{
    const int t = blockIdx.x*blockDim.x + threadIdx.x;  // BB*DI*16 threads
    const int s  = t & 15;
    const int ch = t >> 4;
    const int d  = ch & (DI - 1);
    const int b  = ch >> 10;

    const float a  = -__expf(Alog[d*DSTATE + s]);
    const float Dv = Dp[d];
    const float4* dt4 = reinterpret_cast<const float4*>(g_dtT + (b*DI + d)*LSEQ);
    const float4* xc4 = reinterpret_cast<const float4*>(g_xcT + (b*DI + d)*LSEQ);
    const float2* bcp = reinterpret_cast<const float2*>(g_bc) + (b*LSEQ)*16 + s;
    const float* zp  = g_xz + (size_t)(b*LSEQ)*2*DI + DI + d;
    float* yg = g_yg + (size_t)(b*LSEQ)*DI + d;

    float zc[4] = {0.f, 0.f, 0.f, 0.f};
    if (s == 0) {
#pragma unroll
        for (int j = 0; j < 4; j++) zc[j] = zp[(size_t)j*2*DI];
    }

    float h = 0.f;
    for (int l4 = 0; l4 < LSEQ/4; ++l4) {
        float zn[4] = {0.f, 0.f, 0.f, 0.f};
        if (s == 0 && l4 + 1 < LSEQ/4) {
#pragma unroll
            for (int j = 0; j < 4; j++)
                zn[j] = zp[(size_t)((l4+1)*4 + j)*2*DI];
        }
        float4 dtv = dt4[l4];
        float4 xcv = xc4[l4];
        const float* dts = &dtv.x;
        const float* xcs = &xcv.x;
        float yv[4];
#pragma unroll
        for (int j = 0; j < 4; j++) {
            float dtj = dts[j], xcj = xcs[j];
            float2 bcv = bcp[(l4*4 + j)*16];
            float e = __expf(a * dtj);
            h = fmaf(e, h, dtj * bcv.x * xcj);
            float v = h * bcv.y;
            v += __shfl_xor_sync(0xffffffffu, v, 8, 16);
            v += __shfl_xor_sync(0xffffffffu, v, 4, 16);
            v += __shfl_xor_sync(0xffffffffu, v, 2, 16);
            v += __shfl_xor_sync(0xffffffffu, v, 1, 16);
            yv[j] = v + Dv * xcj;
        }
        if (s == 0) {
#pragma unroll
            for (int j = 0; j < 4; j++)
                yg[(size_t)(l4*4 + j)*DI] = roundtf(yv[j] * siluf(zc[j]));
#pragma unroll
            for (int j = 0; j < 4; j++) zc[j] = zn[j];
        }
    }
}

// ---------------- host driver -----------------------------------------------------
extern "C" void kernel_launch(void* const* d_in, const int* in_sizes, int n_in,
                              void* d_out, int out_size)
{
    const float* x    = (const float*)d_in[0];
    const float* ipw  = (const float*)d_in[1];
    const float* cw   = (const float*)d_in[2];
    const float* cb   = (const float*)d_in[3];
    const float* xpw  = (const float*)d_in[4];
    const float* dpw  = (const float*)d_in[5];
    const float* dpb  = (const float*)d_in[6];
    const float* Alog = (const float*)d_in[7];
    const float* Dp   = (const float*)d_in[8];
    const float* opw  = (const float*)d_in[9];
    const float* w1   = (const float*)d_in[10];
    const float* b1   = (const float*)d_in[11];
    const float* w2   = (const float*)d_in[12];
    const float* b2   = (const float*)d_in[13];
    float* out = (float*)d_out;

    const int GEMM_SMEM = 2*2*128*36*4;  // 73728 bytes
    cudaFuncSetAttribute(tf32_gemm_async,
                         cudaFuncAttributeMaxDynamicSharedMemorySize, GEMM_SMEM);

    float *p_xz, *p_xc, *p_dbl, *p_bc, *p_yg, *p_x1, *p_x2, *p_ff;
    float *p_rx, *p_ripw, *p_ropw, *p_rw1, *p_rw2;
    cudaGetSymbolAddress((void**)&p_xz,  g_xz);
    cudaGetSymbolAddress((void**)&p_xc,  g_xc);
    cudaGetSymbolAddress((void**)&p_dbl, g_dbl);
    cudaGetSymbolAddress((void**)&p_bc,  g_bc);
    cudaGetSymbolAddress((void**)&p_yg,  g_yg);
    cudaGetSymbolAddress((void**)&p_x1,  g_x1);
    cudaGetSymbolAddress((void**)&p_x2,  g_x2);
    cudaGetSymbolAddress((void**)&p_ff,  g_ff);
    cudaGetSymbolAddress((void**)&p_rx,   g_rx);
    cudaGetSymbolAddress((void**)&p_ripw, g_ripw);
    cudaGetSymbolAddress((void**)&p_ropw, g_ropw);
    cudaGetSymbolAddress((void**)&p_rw1,  g_rw1);
    cudaGetSymbolAddress((void**)&p_rw2,  g_rw2);

    // pre-round all GEMM operands to tf32 in ONE launch
    const int n_x   = M_TOT*DM/4;
    const int n_ipw = NL*2*DI*DM/4;
    const int n_opw = NL*DM*DI/4;
    const int n_w1  = FF*DM/4;
    const int n_w2  = DM*FF/4;
    const int n_tot = n_x + n_ipw + n_opw + n_w1 + n_w2;
    round_all_kernel<<<(n_tot + 255)/256, 256>>>(
        x, p_rx, n_x, ipw, p_ripw, n_ipw, opw, p_ropw, n_opw,
        w1, p_rw1, n_w1, w2, p_rw2, n_w2);

    const float* lin = p_rx;
    float* louts[2] = {p_x1, p_x2};
    for (int i = 0; i < NL; i++) {
        // 1) in_proj: xz = x @ ipw^T (tensor; output NOT rounded — feeds fp32 ops)
        tf32_gemm_async<<<dim3(2*DI/128, M_TOT/128), 256, GEMM_SMEM>>>(
            lin, p_ripw + i*2*DI*DM, nullptr, nullptr, p_xz, M_TOT, 2*DI, DM, 0, 0);
        // 2) causal depthwise conv + silu (-> g_xc, g_xcT)
        conv_silu_kernel<<<dim3(DI/32, LSEQ/32, BB), dim3(32,8)>>>(cw + i*DI*4, cb + i*DI);
        // 3) x_proj split-K x16 (partials in g_ff scratch) + reduce/route
        xproj_part_kernel<<<dim3(KSPLIT, M_TOT/64), 256>>>(p_xc, xpw + i*64*DI, p_ff);
        xproj_reduce_kernel<<<(M_TOT*16)/256, 256>>>(p_ff, p_dbl, p_bc);
        // 4) dt = softplus(dbl[:, :32] @ dpw^T + dpb) -> g_dtT
        dtproj_kernel<<<dim3(DI/32, LSEQ/32, BB), dim3(32,8)>>>(dpw + i*DI*DTR, dpb + i*DI);
        // 5) selective scan + fused gating -> g_yg (tf32-rounded)
        scan_gate_kernel<<<(BB*DI*16)/256, 256>>>(Alog + i*DI*DSTATE, Dp + i*DI);
        // 6) out_proj (+residual on layer 1); output rounded (feeds next GEMM)
        tf32_gemm_async<<<dim3(DM/128, M_TOT/128), 256, GEMM_SMEM>>>(
            p_yg, p_ropw + i*DM*DI, nullptr, (i == NL-1) ? x : nullptr,
            louts[i], M_TOT, DM, DI, 0, 1);
        lin = louts[i];
    }
    // MLP: relu(x2@w1^T + b1) rounded -> @ w2^T + b2 (final output NOT rounded)
    tf32_gemm_async<<<dim3(FF/128, M_TOT/128), 256, GEMM_SMEM>>>(
        p_x2, p_rw1, b1, nullptr, p_ff, M_TOT, FF, DM, 1, 1);
    tf32_gemm_async<<<dim3(DM/128, M_TOT/128), 256, GEMM_SMEM>>>(
        p_ff, p_rw2, b2, nullptr, out, M_TOT, DM, FF, 0, 0);
}

// round 13
// speedup vs baseline: 1.5378x; 1.5378x over previous
#include <cuda_runtime.h>
#include <cstdint>

#define BB 2
#define LSEQ 2048
#define DM 512
#define DI 1024
#define DSTATE 16
#define DTR 32
#define FF 1024
#define NL 2
#define M_TOT (BB*LSEQ)   // 4096
#define KSPLIT 16

// ---------------- scratch (static device globals; no allocation) ----------------
__device__ float g_xz [BB*LSEQ*2*DI];   // in_proj output: [B,L,2*DI] (xin | z)
__device__ float g_xc [BB*LSEQ*DI];     // conv+silu, [B,L,DI]
__device__ float g_xcT[BB*LSEQ*DI];     // conv+silu, transposed [B,DI,L]
__device__ float g_dbl[BB*LSEQ*64];     // x_proj dt cols [B*L][64-stride] (0..31 used)
__device__ float g_bc [BB*LSEQ*32];     // interleaved (B,C) pairs [B*L][16] float2
__device__ float g_dtT[BB*LSEQ*DI];     // softplus(dt) transposed [B,DI,L]
__device__ float g_yT [BB*LSEQ*DI];     // scan output transposed [B,DI,L]
__device__ float g_yg [BB*LSEQ*DI];     // gated y [B,L,DI] (tf32-rounded)
__device__ float g_x1 [BB*LSEQ*DM];
__device__ float g_x2 [BB*LSEQ*DM];
__device__ float g_ff [BB*LSEQ*FF];     // MLP hidden; ALSO xproj split-K scratch (16MB)
// tf32-rounded copies of GEMM operands
__device__ float g_rx  [M_TOT*DM];
__device__ float g_ripw[NL*2*DI*DM];
__device__ float g_ropw[NL*DM*DI];
__device__ float g_rw1 [FF*DM];
__device__ float g_rw2 [DM*FF];

__device__ __forceinline__ float siluf(float x) { return x / (1.f + __expf(-x)); }

__device__ __forceinline__ uint32_t f2tf32(float x) {
    uint32_t r;
    asm("cvt.rna.tf32.f32 %0, %1;" : "=r"(r) : "f"(x));
    return r;
}
__device__ __forceinline__ float roundtf(float x) { return __uint_as_float(f2tf32(x)); }

__device__ __forceinline__ void mma_tf32(float* d, const uint32_t* a, const uint32_t* b) {
    asm volatile(
        "mma.sync.aligned.m16n8k8.row.col.f32.tf32.tf32.f32 "
        "{%0,%1,%2,%3}, {%4,%5,%6,%7}, {%8,%9}, {%0,%1,%2,%3};"
        : "+f"(d[0]), "+f"(d[1]), "+f"(d[2]), "+f"(d[3])
        : "r"(a[0]), "r"(a[1]), "r"(a[2]), "r"(a[3]), "r"(b[0]), "r"(b[1]));
}

__device__ __forceinline__ void cp16(void* smem_dst, const void* gptr) {
    uint32_t s = (uint32_t)__cvta_generic_to_shared(smem_dst);
    asm volatile("cp.async.cg.shared.global [%0], [%1], 16;" :: "r"(s), "l"(gptr));
}

__device__ __forceinline__ void ldsm_x4(uint32_t& r0, uint32_t& r1, uint32_t& r2, uint32_t& r3,
                                        uint32_t addr) {
    asm volatile("ldmatrix.sync.aligned.m8n8.x4.shared.b16 {%0,%1,%2,%3}, [%4];"
        : "=r"(r0), "=r"(r1), "=r"(r2), "=r"(r3) : "r"(addr));
}
__device__ __forceinline__ void ldsm_x2(uint32_t& r0, uint32_t& r1, uint32_t addr) {
    asm volatile("ldmatrix.sync.aligned.m8n8.x2.shared.b16 {%0,%1}, [%2];"
        : "=r"(r0), "=r"(r1) : "r"(addr));
}

// ---------------- fused tf32 rounding over 5 segments -----------------------------
__global__ void round_all_kernel(const float* a0, float* b0, int n0,
                                 const float* a1, float* b1, int n1,
                                 const float* a2, float* b2, int n2,
                                 const float* a3, float* b3, int n3,
                                 const float* a4, float* b4, int n4)
{
    int i = blockIdx.x*blockDim.x + threadIdx.x;
    const float* src; float* dst;
    if (i < n0)              { src = a0; dst = b0; }
    else if ((i -= n0) < n1) { src = a1; dst = b1; }
    else if ((i -= n1) < n2) { src = a2; dst = b2; }
    else if ((i -= n2) < n3) { src = a3; dst = b3; }
    else if ((i -= n3) < n4) { src = a4; dst = b4; }
    else return;
    float4 v = reinterpret_cast<const float4*>(src)[i];
    v.x = roundtf(v.x); v.y = roundtf(v.y); v.z = roundtf(v.z); v.w = roundtf(v.w);
    reinterpret_cast<float4*>(dst)[i] = v;
}

// ---------------- TF32 GEMM: 2-stage cp.async + ldmatrix (measured-good) ----------
// C = A * W^T (+bias)(+Cadd)(relu)(roundOut).  A,W pre-rounded to tf32 values.
// A:[M,K] rm, W:[N,K] rm, C:[M,N]. Block 128x128x32, 8 warps, warp tile 64x32.
// Requires: M%128==0, N%128==0, K%32==0. Dynamic smem: 73728 bytes.
__global__ __launch_bounds__(256, 2)
void tf32_gemm_async(const float* __restrict__ A, const float* __restrict__ W,
                     const float* __restrict__ bias, const float* __restrict__ Cadd,
                     float* __restrict__ C, int M, int N, int K, int relu, int roundOut)
{
    extern __shared__ __align__(16) float smem[];
    float* As = smem;                 // [2][128*36]
    float* Bs = smem + 2*128*36;      // [2][128*36]

    const int tid  = threadIdx.x;
    const int warp = tid >> 5, lane = tid & 31;
    const int g = lane >> 2, t = lane & 3;
    const int wm = (warp >> 2) * 64;   // 0 or 64
    const int wn = (warp & 3) * 32;    // 0..96
    const int bm = blockIdx.y * 128;
    const int bn = blockIdx.x * 128;

    // per-lane ldmatrix address offsets (bytes)
    const int rowA = (lane & 7) + (((lane >> 3) & 1) << 3);
    const int colA = ((lane >> 4) & 1) << 2;
    const uint32_t offA = (uint32_t)(rowA*36 + colA) * 4u;
    const int lb = lane & 15;
    const uint32_t offB = (uint32_t)((lb & 7)*36 + ((lb >> 3) << 2)) * 4u;

    const uint32_t As_u = (uint32_t)__cvta_generic_to_shared(As);
    const uint32_t Bs_u = (uint32_t)__cvta_generic_to_shared(Bs);
    const uint32_t STAGE = 128*36*4;

    float d[4][4][4];
#pragma unroll
    for (int mi = 0; mi < 4; mi++)
#pragma unroll
        for (int ni = 0; ni < 4; ni++)
#pragma unroll
            for (int r = 0; r < 4; r++) d[mi][ni][r] = 0.f;

    auto issue_tile = [&](int stage, int k0) {
#pragma unroll
        for (int i = 0; i < 4; i++) {
            int linear = tid + i*256;          // 0..1023 float4 slots
            int m  = linear >> 3;
            int kc = (linear & 7) * 4;
            cp16(&As[stage*128*36 + m*36 + kc], &A[(bm + m)*K + k0 + kc]);
            cp16(&Bs[stage*128*36 + m*36 + kc], &W[(bn + m)*K + k0 + kc]);
        }
    };

    issue_tile(0, 0);
    asm volatile("cp.async.commit_group;");

    const int KT = K >> 5;
    for (int kt = 0; kt < KT; kt++) {
        const int cur = kt & 1;
        if (kt + 1 < KT) {
            issue_tile(cur ^ 1, (kt + 1) << 5);
            asm volatile("cp.async.commit_group;");
            asm volatile("cp.async.wait_group 1;");
        } else {
            asm volatile("cp.async.wait_group 0;");
        }
        __syncthreads();

        const uint32_t Acur = As_u + cur*STAGE;
        const uint32_t Bcur = Bs_u + cur*STAGE;
#pragma unroll
        for (int ks = 0; ks < 4; ks++) {
            const int kk = ks * 8;
            uint32_t a[4][4], b[4][2];
#pragma unroll
            for (int mi = 0; mi < 4; mi++)
                ldsm_x4(a[mi][0], a[mi][1], a[mi][2], a[mi][3],
                        Acur + (uint32_t)(((wm + mi*16)*36 + kk) << 2) + offA);
#pragma unroll
            for (int ni = 0; ni < 4; ni++)
                ldsm_x2(b[ni][0], b[ni][1],
                        Bcur + (uint32_t)(((wn + ni*8)*36 + kk) << 2) + offB);
#pragma unroll
            for (int mi = 0; mi < 4; mi++)
#pragma unroll
                for (int ni = 0; ni < 4; ni++)
                    mma_tf32(d[mi][ni], a[mi], b[ni]);
        }
        __syncthreads();
    }

    // epilogue: c0=(g,2t) c1=(g,2t+1) c2=(g+8,2t) c3=(g+8,2t+1)
#pragma unroll
    for (int mi = 0; mi < 4; mi++) {
        int row0 = bm + wm + mi*16 + g;
        int row1 = row0 + 8;
#pragma unroll
        for (int ni = 0; ni < 4; ni++) {
            int col = bn + wn + ni*8 + 2*t;
            float c0 = d[mi][ni][0], c1 = d[mi][ni][1];
            float c2 = d[mi][ni][2], c3 = d[mi][ni][3];
            if (bias) {
                float b0 = bias[col], b1 = bias[col+1];
                c0 += b0; c1 += b1; c2 += b0; c3 += b1;
            }
            if (Cadd) {
                float2 r0 = *reinterpret_cast<const float2*>(&Cadd[row0*N + col]);
                float2 r1 = *reinterpret_cast<const float2*>(&Cadd[row1*N + col]);
                c0 += r0.x; c1 += r0.y; c2 += r1.x; c3 += r1.y;
            }
            if (relu) {
                c0 = fmaxf(c0, 0.f); c1 = fmaxf(c1, 0.f);
                c2 = fmaxf(c2, 0.f); c3 = fmaxf(c3, 0.f);
            }
            if (roundOut) {
                c0 = roundtf(c0); c1 = roundtf(c1);
                c2 = roundtf(c2); c3 = roundtf(c3);
            }
            *reinterpret_cast<float2*>(&C[row0*N + col]) = make_float2(c0, c1);
            *reinterpret_cast<float2*>(&C[row1*N + col]) = make_float2(c2, c3);
        }
    }
}

// ---------------- x_proj split-K partials: proven sgemm body, K chunk per block ---
// grid (KSPLIT, M_TOT/64). part[(ks*M_TOT + row)*64 + col] = A[rows, kchunk] @ W^T.
__global__ __launch_bounds__(256)
void xproj_part_kernel(const float* __restrict__ A, const float* __restrict__ W,
                       float* __restrict__ part)
{
    constexpr int BM = 64, BN = 64, BK = 8, TM = 4, TN = 4;
    constexpr int THREADS = (BM/TM)*(BN/TN);
    __shared__ __align__(16) float As[BK][BM];
    __shared__ __align__(16) float Bs[BK][BN];
    const int tid = threadIdx.x;
    const int ks = blockIdx.x;
    const int bm = blockIdx.y * BM;
    const int kbeg = ks * (DI / KSPLIT);
    const int kend = kbeg + (DI / KSPLIT);
    const int tni = tid % (BN/TN);
    const int tmi = tid / (BN/TN);

    float acc[TM][TN];
#pragma unroll
    for (int i = 0; i < TM; i++)
#pragma unroll
        for (int j = 0; j < TN; j++) acc[i][j] = 0.f;

    for (int k0 = kbeg; k0 < kend; k0 += BK) {
#pragma unroll
        for (int i = 0; i < (BM*BK)/THREADS; i++) {
            int idx = tid + i*THREADS;
            int m = idx / BK, k = idx % BK;
            As[k][m] = A[(bm + m)*DI + k0 + k];
        }
#pragma unroll
        for (int i = 0; i < (BN*BK)/THREADS; i++) {
            int idx = tid + i*THREADS;
            int n = idx / BK, k = idx % BK;
            Bs[k][n] = W[n*DI + k0 + k];
        }
        __syncthreads();
#pragma unroll
        for (int k = 0; k < BK; k++) {
            float rm[TM], rn[TN];
#pragma unroll
            for (int i = 0; i < TM/4; i++) {
                float4 v = *reinterpret_cast<const float4*>(&As[k][tmi*TM + 4*i]);
                rm[4*i] = v.x; rm[4*i+1] = v.y; rm[4*i+2] = v.z; rm[4*i+3] = v.w;
            }
#pragma unroll
            for (int i = 0; i < TN/4; i++) {
                float4 v = *reinterpret_cast<const float4*>(&Bs[k][tni*TN + 4*i]);
                rn[4*i] = v.x; rn[4*i+1] = v.y; rn[4*i+2] = v.z; rn[4*i+3] = v.w;
            }
#pragma unroll
            for (int i = 0; i < TM; i++)
#pragma unroll
                for (int j = 0; j < TN; j++)
                    acc[i][j] = fmaf(rm[i], rn[j], acc[i][j]);
        }
        __syncthreads();
    }
#pragma unroll
    for (int i = 0; i < TM; i++) {
        int row = bm + tmi*TM + i;
#pragma unroll
        for (int j = 0; j < TN/4; j++) {
            float4 v = make_float4(acc[i][4*j], acc[i][4*j+1], acc[i][4*j+2], acc[i][4*j+3]);
            *reinterpret_cast<float4*>(&part[((size_t)ks*M_TOT + row)*64 + tni*TN + 4*j]) = v;
        }
    }
}

// ---------------- x_proj reduce: sum KSPLIT partials, route dt / interleaved bc ---
__global__ void xproj_reduce_kernel(const float* __restrict__ part,
                                    float* __restrict__ dbl, float* __restrict__ bc)
{
    int i = blockIdx.x*blockDim.x + threadIdx.x;   // M_TOT*16 threads
    int row = i >> 4, cg = i & 15;                 // cg = col/4
    const float4* p = reinterpret_cast<const float4*>(part);
    float4 s = p[((size_t)0*M_TOT + row)*16 + cg];
#pragma unroll
    for (int ks = 1; ks < KSPLIT; ks++) {
        float4 v = p[((size_t)ks*M_TOT + row)*16 + cg];
        s.x += v.x; s.y += v.y; s.z += v.z; s.w += v.w;
    }
    int col = cg * 4;
    if (col < 32) {
        *reinterpret_cast<float4*>(&dbl[row*64 + col]) = s;
    } else if (col < 48) {
        int sidx = col - 32;
        bc[(row*16 + sidx + 0)*2] = s.x;
        bc[(row*16 + sidx + 1)*2] = s.y;
        bc[(row*16 + sidx + 2)*2] = s.z;
        bc[(row*16 + sidx + 3)*2] = s.w;
    } else {
        int sidx = col - 48;
        bc[(row*16 + sidx + 0)*2 + 1] = s.x;
        bc[(row*16 + sidx + 1)*2 + 1] = s.y;
        bc[(row*16 + sidx + 2)*2 + 1] = s.z;
        bc[(row*16 + sidx + 3)*2 + 1] = s.w;
    }
}

// ---------------- causal depthwise conv(4) + silu; writes [B,L,DI] and [B,DI,L] ---
__global__ void conv_silu_kernel(const float* __restrict__ cw, const float* __restrict__ cb)
{
    __shared__ float sx[35][32];
    __shared__ float so[32][33];
    const int b = blockIdx.z, l0 = blockIdx.y*32, d0 = blockIdx.x*32;
    const int tx = threadIdx.x, ty = threadIdx.y;
    const int tid = ty*32 + tx;

    for (int i = tid; i < 35*32; i += 256) {
        int r = i >> 5, dd = i & 31;
        int l = l0 - 3 + r;
        sx[r][dd] = (l >= 0) ? g_xz[(b*LSEQ + l)*2*DI + d0 + dd] : 0.f;
    }
    const float w0 = cw[(d0+tx)*4+0], w1 = cw[(d0+tx)*4+1];
    const float w2 = cw[(d0+tx)*4+2], w3 = cw[(d0+tx)*4+3];
    const float bias = cb[d0+tx];
    __syncthreads();
#pragma unroll
    for (int j = 0; j < 4; j++) {
        int ll = ty + j*8;
        float a = bias + sx[ll][tx]*w0 + sx[ll+1][tx]*w1 + sx[ll+2][tx]*w2 + sx[ll+3][tx]*w3;
        float v = siluf(a);
        g_xc[(b*LSEQ + l0 + ll)*DI + d0 + tx] = v;
        so[ll][tx] = v;
    }
    __syncthreads();
#pragma unroll
    for (int j = 0; j < 4; j++) {
        int dd = ty + j*8;
        g_xcT[(b*DI + d0 + dd)*LSEQ + l0 + tx] = so[tx][dd];
    }
}

// ---------------- dt = softplus(dbl[:, :32] @ dpw^T + dpb), transposed store ------
__global__ void dtproj_kernel(const float* __restrict__ dpw, const float* __restrict__ dpb)
{
    __shared__ float sdbl[32][33];
    __shared__ float sw  [32][33];
    __shared__ float so  [32][33];
    const int b = blockIdx.z, l0 = blockIdx.y*32, d0 = blockIdx.x*32;
    const int tx = threadIdx.x, ty = threadIdx.y;
    const int tid = ty*32 + tx;

    for (int i = tid; i < 1024; i += 256) {
        int r = i >> 5, c = i & 31;
        sdbl[r][c] = g_dbl[(b*LSEQ + l0 + r)*64 + c];
        sw[r][c]   = dpw[(d0 + r)*32 + c];
    }
    __syncthreads();
    const float bias = dpb[d0 + tx];
#pragma unroll
    for (int j = 0; j < 4; j++) {
        int ll = ty + j*8;
        float a = bias;
#pragma unroll
        for (int r = 0; r < 32; r++) a = fmaf(sdbl[ll][r], sw[tx][r], a);
        float sp = (a > 20.f) ? a : log1pf(__expf(a));
        so[ll][tx] = sp;
    }
    __syncthreads();
#pragma unroll
    for (int j = 0; j < 4; j++) {
        int dd = ty + j*8;
        g_dtT[(b*DI + d0 + dd)*LSEQ + l0 + tx] = so[tx][dd];
    }
}

// ---------------- selective scan: thread per (b, d, s); 16-lane reduce ------------
__global__ void scan_kernel(const float* __restrict__ Alog, const float* __restrict__ Dp)
{
    const int t = blockIdx.x*blockDim.x + threadIdx.x;  // BB*DI*16 threads
    const int s  = t & 15;
    const int ch = t >> 4;
    const int d  = ch & (DI - 1);
    const int b  = ch >> 10;

    const float a  = -__expf(Alog[d*DSTATE + s]);
    const float Dv = Dp[d];
    const float4* dt4 = reinterpret_cast<const float4*>(g_dtT + (b*DI + d)*LSEQ);
    const float4* xc4 = reinterpret_cast<const float4*>(g_xcT + (b*DI + d)*LSEQ);
    const float2* bcp = reinterpret_cast<const float2*>(g_bc) + (b*LSEQ)*16 + s;
    float4* yo = reinterpret_cast<float4*>(g_yT + (b*DI + d)*LSEQ);

    float h = 0.f;
    for (int l4 = 0; l4 < LSEQ/4; ++l4) {
        float4 dtv = dt4[l4];
        float4 xcv = xc4[l4];
        const float* dts = &dtv.x;
        const float* xcs = &xcv.x;
        float yv[4];
#pragma unroll
        for (int j = 0; j < 4; j++) {
            float dtj = dts[j], xcj = xcs[j];
            float2 bcv = bcp[(l4*4 + j)*16];
            float e = __expf(a * dtj);
            h = fmaf(e, h, dtj * bcv.x * xcj);
            float v = h * bcv.y;
            v += __shfl_xor_sync(0xffffffffu, v, 8, 16);
            v += __shfl_xor_sync(0xffffffffu, v, 4, 16);
            v += __shfl_xor_sync(0xffffffffu, v, 2, 16);
            v += __shfl_xor_sync(0xffffffffu, v, 1, 16);
            yv[j] = v + Dv * xcj;
        }
        if (s == 0) yo[l4] = make_float4(yv[0], yv[1], yv[2], yv[3]);
    }
}

// ---------------- gating: yg = yT * silu(z), tf32-rounded (feeds out_proj) --------
__global__ void gate_kernel()
{
    __shared__ float sy[32][33];
    const int b = blockIdx.z, l0 = blockIdx.y*32, d0 = blockIdx.x*32;
    const int tx = threadIdx.x, ty = threadIdx.y;
#pragma unroll
    for (int j = 0; j < 4; j++) {
        int dd = ty + j*8;
        sy[tx][dd] = g_yT[(b*DI + d0 + dd)*LSEQ + l0 + tx];
    }
    __syncthreads();
#pragma unroll
    for (int j = 0; j < 4; j++) {
        int ll = ty + j*8;
        float z = g_xz[(b*LSEQ + l0 + ll)*2*DI + DI + d0 + tx];
        g_yg[(b*LSEQ + l0 + ll)*DI + d0 + tx] = roundtf(sy[ll][tx] * siluf(z));
    }
}

// ---------------- host driver -----------------------------------------------------
extern "C" void kernel_launch(void* const* d_in, const int* in_sizes, int n_in,
                              void* d_out, int out_size)
{
    const float* x    = (const float*)d_in[0];
    const float* ipw  = (const float*)d_in[1];
    const float* cw   = (const float*)d_in[2];
    const float* cb   = (const float*)d_in[3];
    const float* xpw  = (const float*)d_in[4];
    const float* dpw  = (const float*)d_in[5];
    const float* dpb  = (const float*)d_in[6];
    const float* Alog = (const float*)d_in[7];
    const float* Dp   = (const float*)d_in[8];
    const float* opw  = (const float*)d_in[9];
    const float* w1   = (const float*)d_in[10];
    const float* b1   = (const float*)d_in[11];
    const float* w2   = (const float*)d_in[12];
    const float* b2   = (const float*)d_in[13];
    float* out = (float*)d_out;

    const int GEMM_SMEM = 2*2*128*36*4;  // 73728 bytes
    cudaFuncSetAttribute(tf32_gemm_async,
                         cudaFuncAttributeMaxDynamicSharedMemorySize, GEMM_SMEM);

    float *p_xz, *p_xc, *p_dbl, *p_bc, *p_yg, *p_x1, *p_x2, *p_ff;
    float *p_rx, *p_ripw, *p_ropw, *p_rw1, *p_rw2;
    cudaGetSymbolAddress((void**)&p_xz,  g_xz);
    cudaGetSymbolAddress((void**)&p_xc,  g_xc);
    cudaGetSymbolAddress((void**)&p_dbl, g_dbl);
    cudaGetSymbolAddress((void**)&p_bc,  g_bc);
    cudaGetSymbolAddress((void**)&p_yg,  g_yg);
    cudaGetSymbolAddress((void**)&p_x1,  g_x1);
    cudaGetSymbolAddress((void**)&p_x2,  g_x2);
    cudaGetSymbolAddress((void**)&p_ff,  g_ff);
    cudaGetSymbolAddress((void**)&p_rx,   g_rx);
    cudaGetSymbolAddress((void**)&p_ripw, g_ripw);
    cudaGetSymbolAddress((void**)&p_ropw, g_ropw);
    cudaGetSymbolAddress((void**)&p_rw1,  g_rw1);
    cudaGetSymbolAddress((void**)&p_rw2,  g_rw2);

    // pre-round all GEMM operands to tf32 in ONE launch
    const int n_x   = M_TOT*DM/4;
    const int n_ipw = NL*2*DI*DM/4;
    const int n_opw = NL*DM*DI/4;
    const int n_w1  = FF*DM/4;
    const int n_w2  = DM*FF/4;
    const int n_tot = n_x + n_ipw + n_opw + n_w1 + n_w2;
    round_all_kernel<<<(n_tot + 255)/256, 256>>>(
        x, p_rx, n_x, ipw, p_ripw, n_ipw, opw, p_ropw, n_opw,
        w1, p_rw1, n_w1, w2, p_rw2, n_w2);

    const float* lin = p_rx;
    float* louts[2] = {p_x1, p_x2};
    for (int i = 0; i < NL; i++) {
        // 1) in_proj: xz = x @ ipw^T (tensor; output NOT rounded — feeds fp32 ops)
        tf32_gemm_async<<<dim3(2*DI/128, M_TOT/128), 256, GEMM_SMEM>>>(
            lin, p_ripw + i*2*DI*DM, nullptr, nullptr, p_xz, M_TOT, 2*DI, DM, 0, 0);
        // 2) causal depthwise conv + silu (-> g_xc, g_xcT)
        conv_silu_kernel<<<dim3(DI/32, LSEQ/32, BB), dim3(32,8)>>>(cw + i*DI*4, cb + i*DI);
        // 3) x_proj split-K x16 (partials in g_ff scratch) + reduce/route
        xproj_part_kernel<<<dim3(KSPLIT, M_TOT/64), 256>>>(p_xc, xpw + i*64*DI, p_ff);
        xproj_reduce_kernel<<<(M_TOT*16)/256, 256>>>(p_ff, p_dbl, p_bc);
        // 4) dt = softplus(dbl[:, :32] @ dpw^T + dpb) -> g_dtT
        dtproj_kernel<<<dim3(DI/32, LSEQ/32, BB), dim3(32,8)>>>(dpw + i*DI*DTR, dpb + i*DI);
        // 5) selective scan -> g_yT
        scan_kernel<<<(BB*DI*16)/256, 256>>>(Alog + i*DI*DSTATE, Dp + i*DI);
        // 6) gating -> g_yg (tf32-rounded: feeds out_proj)
        gate_kernel<<<dim3(DI/32, LSEQ/32, BB), dim3(32,8)>>>();
        // 7) out_proj (+residual on layer 1); output rounded (feeds next GEMM)
        tf32_gemm_async<<<dim3(DM/128, M_TOT/128), 256, GEMM_SMEM>>>(
            p_yg, p_ropw + i*DM*DI, nullptr, (i == NL-1) ? x : nullptr,
            louts[i], M_TOT, DM, DI, 0, 1);
        lin = louts[i];
    }
    // MLP: relu(x2@w1^T + b1) rounded -> @ w2^T + b2 (final output NOT rounded)
    tf32_gemm_async<<<dim3(FF/128, M_TOT/128), 256, GEMM_SMEM>>>(
        p_x2, p_rw1, b1, nullptr, p_ff, M_TOT, FF, DM, 1, 1);
    tf32_gemm_async<<<dim3(DM/128, M_TOT/128), 256, GEMM_SMEM>>>(
        p_ff, p_rw2, b2, nullptr, out, M_TOT, DM, FF, 0, 0);
}